// round 15
// baseline (speedup 1.0000x reference)
#include <cuda_runtime.h>
#include <cuda_bf16.h>

#define NPTS  1024
#define CAP   192
#define R2    (0.15f * 0.15f)

// PWL table for the 6 single-axis rotations (+x,-x,+y,-y,+z,-z):
// A_o(t) = alpha[rot][seg][o] + beta[rot][seg][o] * t,
// seg = #breakpoints below t (order-invariant -> breakpoints stay UNSORTED).
__device__ float2 g_tab[6 * 33 * 64];
__device__ float  g_bp[6 * 32];        // unsorted breakpoints per rot

__global__ void build_tab(const float* __restrict__ W1,
                          const float* __restrict__ b1,
                          const float* __restrict__ W2)
{
    const int rot  = blockIdx.x;           // 0..5
    const int axis = rot >> 1;
    const float sgn = (rot & 1) ? -1.f : 1.f;
    __shared__ float e[32], bb[32], bps[32];
    __shared__ int   rk[32];
    const int t = threadIdx.x;             // 256 threads

    if (t < 32) {
        float ec = sgn * W1[t * 3 + axis];
        float bc = b1[t];
        float bp;
        if (ec != 0.f)      bp = -bc / ec;
        else if (bc > 0.f)  bp = -3.0e38f;  // always active
        else                bp =  3.0e38f;  // never active
        e[t] = ec; bb[t] = bc; bps[t] = bp;
        g_bp[rot * 32 + t] = bp;
    }
    __syncthreads();
    if (t < 32) {
        float bp = bps[t];
        int rank = 0;
        #pragma unroll
        for (int f = 0; f < 32; ++f) {
            float bf = bps[f];
            rank += (bf < bp) || (bf == bp && f < t);
        }
        rk[t] = rank;
    }
    __syncthreads();

    // Fill all 33 segments x 64 rows in parallel. Active-set algebra:
    // e>0: relu on for t > bp  <=> rank < seg; e<0: on for t < bp <=> rank >= seg.
    for (int idx = t; idx < 33 * 64; idx += 256) {
        const int s   = idx >> 6;          // segment 0..32
        const int row = idx & 63;
        const float* w2r = W2 + row * 32;
        float alpha = 0.f, beta = 0.f;
        #pragma unroll
        for (int c = 0; c < 32; ++c) {
            bool act = (e[c] > 0.f) ? (rk[c] < s)
                     : (e[c] < 0.f) ? (rk[c] >= s)
                                    : (bb[c] > 0.f);
            if (act) {
                alpha = fmaf(w2r[c], bb[c], alpha);
                beta  = fmaf(w2r[c], e[c],  beta);
            }
        }
        g_tab[(rot * 33 + s) * 64 + row] = make_float2(alpha, beta);
    }
}

__device__ __forceinline__ unsigned long long ffma2(unsigned long long a,
                                                    unsigned long long b,
                                                    unsigned long long c) {
    unsigned long long d;
    asm("fma.rn.f32x2 %0, %1, %2, %3;" : "=l"(d) : "l"(a), "l"(b), "l"(c));
    return d;
}
__device__ __forceinline__ void unpack2(unsigned long long v, float& lo, float& hi) {
    asm("mov.b64 {%0, %1}, %2;" : "=f"(lo), "=f"(hi) : "l"(v));
}

__global__ __launch_bounds__(64, 12)
void pe_kernel(const float* __restrict__ x, const float* __restrict__ W1,
               const float* __restrict__ b1, const float* __restrict__ W2,
               const float* __restrict__ b2, float* __restrict__ out)
{
    __shared__ float sg[CAP * 3];
    __shared__ float sd2[CAP];
    __shared__ float ssel[63 * 3];
    // per-warp double-buffered tile: 4 full-sign rots x 32 channels
    __shared__ __align__(16) float sh[2][2][128];
    __shared__ int scnt, sselcnt;

    const int tid  = threadIdx.x;
    const int wrp  = tid >> 5;
    const int c    = tid & 31;              // lane = layer-1 channel
    const int row  = c + 32 * wrp;          // this lane's output row
    const int b    = blockIdx.x >> 10;
    const int n    = blockIdx.x & (NPTS - 1);
    const float* xb = x + b * NPTS * 3;

    if (tid == 0) { scnt = 0; sselcnt = 0; }
    __syncthreads();

    const float qx = __ldg(&xb[n * 3 + 0]);
    const float qy = __ldg(&xb[n * 3 + 1]);
    const float qz = __ldg(&xb[n * 3 + 2]);

    // ---- ball query ----
    for (int j = tid; j < NPTS; j += 64) {
        float dx = __ldg(&xb[j * 3 + 0]) - qx;
        float dy = __ldg(&xb[j * 3 + 1]) - qy;
        float dz = __ldg(&xb[j * 3 + 2]) - qz;
        float d2 = dx * dx + dy * dy + dz * dz;
        if (d2 <= R2 && j != n) {
            int p = atomicAdd(&scnt, 1);
            if (p < CAP) {
                sg[p * 3 + 0] = dx; sg[p * 3 + 1] = dy; sg[p * 3 + 2] = dz;
                sd2[p] = d2;
            }
        }
    }
    __syncthreads();

    int cnt = min(scnt, CAP);
    const float* glist = sg;
    int m = cnt;

    // Overflow (>63 in ball): exact rank-select 63 nearest (top_k parity).
    if (cnt > 63) {
        for (int e = tid; e < cnt; e += 64) {
            float de = sd2[e];
            int rank = 0;
            for (int f = 0; f < cnt; ++f) {
                float df = sd2[f];
                rank += (df < de) || (df == de && f < e);
            }
            if (rank < 63) {
                int p = atomicAdd(&sselcnt, 1);
                ssel[p * 3 + 0] = sg[e * 3 + 0];
                ssel[p * 3 + 1] = sg[e * 3 + 1];
                ssel[p * 3 + 2] = sg[e * 3 + 2];
            }
        }
        __syncthreads();
        glist = ssel;
        m = 63;
    }

    // ---- per-lane layer-1 weights (channel = lane) ----
    const float w1x = __ldg(&W1[c * 3 + 0]);
    const float w1y = __ldg(&W1[c * 3 + 1]);
    const float w1z = __ldg(&W1[c * 3 + 2]);
    const float b1c = __ldg(&b1[c]);

    // ---- ONE W2 row per lane (row), channel-pair packed: 32 regs ----
    const unsigned long long* w2row =
        reinterpret_cast<const unsigned long long*>(W2 + row * 32);
    unsigned long long wpk[16];
    #pragma unroll
    for (int q = 0; q < 16; ++q) wpk[q] = __ldg(&w2row[q]);
    const float b2o = __ldg(&b2[row]);

    // breakpoints, one per lane per rot (unsorted; ballot count is order-free)
    float sbp[6];
    #pragma unroll
    for (int r = 0; r < 6; ++r) sbp[r] = g_bp[r * 32 + c];

    // self = A(t=0) from rot 0's table (h(0) = relu(b1), rot-independent)
    float self;
    {
        unsigned mask = __ballot_sync(0xffffffffu, 0.f > sbp[0]);
        int seg = __popc(mask);
        self = g_tab[(0 * 33 + seg) * 64 + row].x;
    }

    float mvf[4], mva[6];
    #pragma unroll
    for (int r = 0; r < 4; ++r) mvf[r] = self;
    #pragma unroll
    for (int r = 0; r < 6; ++r) mva[r] = self;

    float* buf0 = &sh[wrp][0][0];
    float* buf1 = &sh[wrp][1][0];

    // ---- main loop: warps fully independent ----
    for (int k = 0; k < m; ++k) {
        float* buf = (k & 1) ? buf1 : buf0;
        const float gx = glist[k * 3 + 0];
        const float gy = glist[k * 3 + 1];
        const float gz = glist[k * 3 + 2];

        // 6 axis rotations via PWL table: ballot rank + coalesced LDG.64.
        {
            const float ts[6] = {gx, gx, gy, gy, gz, gz};
            #pragma unroll
            for (int r = 0; r < 6; ++r) {
                unsigned mask = __ballot_sync(0xffffffffu, ts[r] > sbp[r]);
                int seg = __popc(mask);
                float2 ab = g_tab[(r * 33 + seg) * 64 + row];
                mva[r] = fmaxf(mva[r], fmaf(ab.y, ts[r], ab.x));
            }
        }

        // 4 full-sign rotations via smem tile (R=1).
        float px = w1x * gx, py = w1y * gy, pz = w1z * gz;
        float a = b1c + px, d = b1c - px;
        float u = py + pz,  v = py - pz;
        buf[0 * 32 + c] = fmaxf(a + u, 0.f);   // (+,+,+)
        buf[1 * 32 + c] = fmaxf(a - u, 0.f);   // (+,-,-)
        buf[2 * 32 + c] = fmaxf(d + v, 0.f);   // (-,+,-)
        buf[3 * 32 + c] = fmaxf(d - v, 0.f);   // (-,-,+)
        __syncwarp();

        unsigned long long acc[4] = {0ull, 0ull, 0ull, 0ull};
        const ulonglong2* hp = reinterpret_cast<const ulonglong2*>(buf);
        #pragma unroll
        for (int q = 0; q < 8; ++q) {
            #pragma unroll
            for (int r = 0; r < 4; ++r) {
                ulonglong2 hv = hp[r * 8 + q];    // rot r, channels 4q..4q+3
                acc[r] = ffma2(hv.x, wpk[2 * q + 0], acc[r]);
                acc[r] = ffma2(hv.y, wpk[2 * q + 1], acc[r]);
            }
        }
        #pragma unroll
        for (int r = 0; r < 4; ++r) {
            float lo, hi; unpack2(acc[r], lo, hi);
            mvf[r] = fmaxf(mvf[r], lo + hi);
        }
    }

    // mean over 24 rots: 4 full (w=1) + 6 axis (w=2) + 8 zero-diag (self)
    float fs = 8.f * fmaxf(self + b2o, 0.f);
    #pragma unroll
    for (int r = 0; r < 4; ++r) fs += fmaxf(mvf[r] + b2o, 0.f);
    #pragma unroll
    for (int r = 0; r < 6; ++r) fs += 2.f * fmaxf(mva[r] + b2o, 0.f);

    out[(b * 64 + row) * NPTS + n] = fs * (1.f / 24.f);
}

extern "C" void kernel_launch(void* const* d_in, const int* in_sizes, int n_in,
                              void* d_out, int out_size)
{
    const float* x  = (const float*)d_in[0];  // [B,1024,3]
    const float* W1 = (const float*)d_in[1];  // [32,3]
    const float* b1 = (const float*)d_in[2];  // [32]
    const float* W2 = (const float*)d_in[3];  // [64,32]
    const float* b2 = (const float*)d_in[4];  // [64]
    float* out = (float*)d_out;               // [B,64,1024]

    build_tab<<<6, 256>>>(W1, b1, W2);

    int total_pts = in_sizes[0] / 3;          // B * 1024
    pe_kernel<<<total_pts, 64>>>(x, W1, b1, W2, b2, out);
}

// round 16
// speedup vs baseline: 1.4270x; 1.4270x over previous
#include <cuda_runtime.h>
#include <cuda_bf16.h>

#define NPTS  1024
#define CAP   192
#define R2    (0.15f * 0.15f)

// PWL table for the 6 single-axis rotations (+x,-x,+y,-y,+z,-z):
// A_o(t) = alpha[rot][seg][o] + beta[rot][seg][o] * t,
// seg = #breakpoints below t (order-invariant -> breakpoints stay UNSORTED).
__device__ float2 g_tab[6 * 33 * 64];
__device__ float  g_bp[6 * 32];        // unsorted breakpoints per rot

// Incremental build: crossing breakpoint rank s-1 flips exactly one channel.
// Per thread (= output row): 32 init FMA + 32 flip updates + 33 stores.
__global__ __launch_bounds__(64)
void build_tab(const float* __restrict__ W1,
               const float* __restrict__ b1,
               const float* __restrict__ W2)
{
    const int rot  = blockIdx.x;           // 0..5
    const int axis = rot >> 1;
    const float sgn = (rot & 1) ? -1.f : 1.f;
    __shared__ float e[32], bb[32], bps[32];
    __shared__ int   ord[32];              // ord[rank] = channel
    __shared__ float w2s[64 * 32];         // W2 staged coalesced (8 KB)
    const int t = threadIdx.x;             // 64 threads; t = output row

    for (int i = t; i < 64 * 32; i += 64) w2s[i] = W2[i];
    if (t < 32) {
        float ec = sgn * W1[t * 3 + axis];
        float bc = b1[t];
        float bp;
        if (ec != 0.f)      bp = -bc / ec;
        else if (bc > 0.f)  bp = -3.0e38f;  // always active
        else                bp =  3.0e38f;  // never active
        e[t] = ec; bb[t] = bc; bps[t] = bp;
        g_bp[rot * 32 + t] = bp;
    }
    __syncthreads();
    if (t < 32) {
        float bp = bps[t];
        int rank = 0;
        #pragma unroll
        for (int f = 0; f < 32; ++f) {
            float bf = bps[f];
            rank += (bf < bp) || (bf == bp && f < t);
        }
        ord[rank] = t;
    }
    __syncthreads();

    const float* w = w2s + t * 32;
    // s = 0: t below all breakpoints -> e<0 channels active, e==0 by sign(b).
    float alpha = 0.f, beta = 0.f;
    #pragma unroll
    for (int c = 0; c < 32; ++c) {
        if (e[c] < 0.f || (e[c] == 0.f && bb[c] > 0.f)) {
            alpha = fmaf(w[c], bb[c], alpha);
            beta  = fmaf(w[c], e[c],  beta);
        }
    }
    g_tab[(rot * 33 + 0) * 64 + t] = make_float2(alpha, beta);

    #pragma unroll
    for (int s = 1; s <= 32; ++s) {
        int cc = ord[s - 1];
        float ec = e[cc];
        if (ec > 0.f) {            // turned ON
            alpha = fmaf(w[cc],  bb[cc], alpha);
            beta  = fmaf(w[cc],  ec,     beta);
        } else if (ec < 0.f) {     // turned OFF
            alpha = fmaf(-w[cc], bb[cc], alpha);
            beta  = fmaf(-w[cc], ec,     beta);
        }                          // e==0: activity never changes
        g_tab[(rot * 33 + s) * 64 + t] = make_float2(alpha, beta);
    }
}

__device__ __forceinline__ unsigned long long ffma2(unsigned long long a,
                                                    unsigned long long b,
                                                    unsigned long long c) {
    unsigned long long d;
    asm("fma.rn.f32x2 %0, %1, %2, %3;" : "=l"(d) : "l"(a), "l"(b), "l"(c));
    return d;
}
__device__ __forceinline__ void unpack2(unsigned long long v, float& lo, float& hi) {
    asm("mov.b64 {%0, %1}, %2;" : "=f"(lo), "=f"(hi) : "l"(v));
}

__global__ __launch_bounds__(64, 12)
void pe_kernel(const float* __restrict__ x, const float* __restrict__ W1,
               const float* __restrict__ b1, const float* __restrict__ W2,
               const float* __restrict__ b2, float* __restrict__ out)
{
    __shared__ float sg[CAP * 3];
    __shared__ float sd2[CAP];
    __shared__ float ssel[63 * 3];
    // per-warp double-buffered tile: 4 full-sign rots x 32 channels
    __shared__ __align__(16) float sh[2][2][128];
    __shared__ int scnt, sselcnt;

    const int tid  = threadIdx.x;
    const int wrp  = tid >> 5;
    const int c    = tid & 31;              // lane = layer-1 channel
    const int row  = c + 32 * wrp;          // this lane's output row
    const int b    = blockIdx.x >> 10;
    const int n    = blockIdx.x & (NPTS - 1);
    const float* xb = x + b * NPTS * 3;

    if (tid == 0) { scnt = 0; sselcnt = 0; }
    __syncthreads();

    const float qx = __ldg(&xb[n * 3 + 0]);
    const float qy = __ldg(&xb[n * 3 + 1]);
    const float qz = __ldg(&xb[n * 3 + 2]);

    // ---- ball query ----
    for (int j = tid; j < NPTS; j += 64) {
        float dx = __ldg(&xb[j * 3 + 0]) - qx;
        float dy = __ldg(&xb[j * 3 + 1]) - qy;
        float dz = __ldg(&xb[j * 3 + 2]) - qz;
        float d2 = dx * dx + dy * dy + dz * dz;
        if (d2 <= R2 && j != n) {
            int p = atomicAdd(&scnt, 1);
            if (p < CAP) {
                sg[p * 3 + 0] = dx; sg[p * 3 + 1] = dy; sg[p * 3 + 2] = dz;
                sd2[p] = d2;
            }
        }
    }
    __syncthreads();

    int cnt = min(scnt, CAP);
    const float* glist = sg;
    int m = cnt;

    // Overflow (>63 in ball): exact rank-select 63 nearest (top_k parity).
    if (cnt > 63) {
        for (int e = tid; e < cnt; e += 64) {
            float de = sd2[e];
            int rank = 0;
            for (int f = 0; f < cnt; ++f) {
                float df = sd2[f];
                rank += (df < de) || (df == de && f < e);
            }
            if (rank < 63) {
                int p = atomicAdd(&sselcnt, 1);
                ssel[p * 3 + 0] = sg[e * 3 + 0];
                ssel[p * 3 + 1] = sg[e * 3 + 1];
                ssel[p * 3 + 2] = sg[e * 3 + 2];
            }
        }
        __syncthreads();
        glist = ssel;
        m = 63;
    }

    // ---- per-lane layer-1 weights (channel = lane) ----
    const float w1x = __ldg(&W1[c * 3 + 0]);
    const float w1y = __ldg(&W1[c * 3 + 1]);
    const float w1z = __ldg(&W1[c * 3 + 2]);
    const float b1c = __ldg(&b1[c]);

    // ---- ONE W2 row per lane (row), channel-pair packed: 32 regs ----
    const unsigned long long* w2row =
        reinterpret_cast<const unsigned long long*>(W2 + row * 32);
    unsigned long long wpk[16];
    #pragma unroll
    for (int q = 0; q < 16; ++q) wpk[q] = __ldg(&w2row[q]);
    const float b2o = __ldg(&b2[row]);

    // breakpoints, one per lane per rot (unsorted; ballot count is order-free)
    float sbp[6];
    #pragma unroll
    for (int r = 0; r < 6; ++r) sbp[r] = g_bp[r * 32 + c];

    // self = A(t=0) from rot 0's table (h(0) = relu(b1), rot-independent)
    float self;
    {
        unsigned mask = __ballot_sync(0xffffffffu, 0.f > sbp[0]);
        int seg = __popc(mask);
        self = g_tab[(0 * 33 + seg) * 64 + row].x;
    }

    float mvf[4], mva[6];
    #pragma unroll
    for (int r = 0; r < 4; ++r) mvf[r] = self;
    #pragma unroll
    for (int r = 0; r < 6; ++r) mva[r] = self;

    float* buf0 = &sh[wrp][0][0];
    float* buf1 = &sh[wrp][1][0];

    // ---- main loop: warps fully independent ----
    for (int k = 0; k < m; ++k) {
        float* buf = (k & 1) ? buf1 : buf0;
        const float gx = glist[k * 3 + 0];
        const float gy = glist[k * 3 + 1];
        const float gz = glist[k * 3 + 2];

        // 6 axis rotations via PWL table: ballot rank + coalesced LDG.64.
        {
            const float ts[6] = {gx, gx, gy, gy, gz, gz};
            #pragma unroll
            for (int r = 0; r < 6; ++r) {
                unsigned mask = __ballot_sync(0xffffffffu, ts[r] > sbp[r]);
                int seg = __popc(mask);
                float2 ab = g_tab[(r * 33 + seg) * 64 + row];
                mva[r] = fmaxf(mva[r], fmaf(ab.y, ts[r], ab.x));
            }
        }

        // 4 full-sign rotations via smem tile (R=1).
        float px = w1x * gx, py = w1y * gy, pz = w1z * gz;
        float a = b1c + px, d = b1c - px;
        float u = py + pz,  v = py - pz;
        buf[0 * 32 + c] = fmaxf(a + u, 0.f);   // (+,+,+)
        buf[1 * 32 + c] = fmaxf(a - u, 0.f);   // (+,-,-)
        buf[2 * 32 + c] = fmaxf(d + v, 0.f);   // (-,+,-)
        buf[3 * 32 + c] = fmaxf(d - v, 0.f);   // (-,-,+)
        __syncwarp();

        unsigned long long acc[4] = {0ull, 0ull, 0ull, 0ull};
        const ulonglong2* hp = reinterpret_cast<const ulonglong2*>(buf);
        #pragma unroll
        for (int q = 0; q < 8; ++q) {
            #pragma unroll
            for (int r = 0; r < 4; ++r) {
                ulonglong2 hv = hp[r * 8 + q];    // rot r, channels 4q..4q+3
                acc[r] = ffma2(hv.x, wpk[2 * q + 0], acc[r]);
                acc[r] = ffma2(hv.y, wpk[2 * q + 1], acc[r]);
            }
        }
        #pragma unroll
        for (int r = 0; r < 4; ++r) {
            float lo, hi; unpack2(acc[r], lo, hi);
            mvf[r] = fmaxf(mvf[r], lo + hi);
        }
    }

    // mean over 24 rots: 4 full (w=1) + 6 axis (w=2) + 8 zero-diag (self)
    float fs = 8.f * fmaxf(self + b2o, 0.f);
    #pragma unroll
    for (int r = 0; r < 4; ++r) fs += fmaxf(mvf[r] + b2o, 0.f);
    #pragma unroll
    for (int r = 0; r < 6; ++r) fs += 2.f * fmaxf(mva[r] + b2o, 0.f);

    out[(b * 64 + row) * NPTS + n] = fs * (1.f / 24.f);
}

extern "C" void kernel_launch(void* const* d_in, const int* in_sizes, int n_in,
                              void* d_out, int out_size)
{
    const float* x  = (const float*)d_in[0];  // [B,1024,3]
    const float* W1 = (const float*)d_in[1];  // [32,3]
    const float* b1 = (const float*)d_in[2];  // [32]
    const float* W2 = (const float*)d_in[3];  // [64,32]
    const float* b2 = (const float*)d_in[4];  // [64]
    float* out = (float*)d_out;               // [B,64,1024]

    build_tab<<<6, 64>>>(W1, b1, W2);

    int total_pts = in_sizes[0] / 3;          // B * 1024
    pe_kernel<<<total_pts, 64>>>(x, W1, b1, W2, b2, out);
}